// round 17
// baseline (speedup 1.0000x reference)
#include <cuda_runtime.h>
#include <cuda_fp16.h>
#include <cstdint>

// Problem constants
#define S_DIM 256
#define B_DIM 128
#define D_DIM 768
#define L_DIM 200
#define V_DIM 8
#define M_DIM (S_DIM * B_DIM)   // 32768
#define N_DIM (L_DIM * V_DIM)   // 1600

// GEMM tiling
#define BM 128                  // rows per CTA tile (one s; local row == batch b)
#define BN 64                   // cols per CTA tile (8 whole labels)
#define KC 64                   // fp16 k per chunk -> 128-byte rows
#define NCHUNK (D_DIM / KC)     // 12
#define NTHREADS 128            // 4 warps, 2x2 warp grid, 64x32 warp tile

#define NTILE_X (N_DIM / BN)    // 25
#define NTILE   (NTILE_X * (M_DIM / BM))   // 6400
#define GRIDX 592               // 148 SMs x 4 CTAs (work-stealing tolerates less)

#define A_BYTES (BM * KC * 2)   // 16384
#define B_BYTES (BN * KC * 2)   //  8192
#define BUF_BYTES (A_BYTES + B_BYTES)          // 24576
#define SMEM_TOTAL (2 * BUF_BYTES)             // 49152 -> 4 CTAs/SM

// Scratch (no runtime allocation allowed)
__device__ __half g_A[(size_t)M_DIM * D_DIM];   // unit-normalized embed
__device__ __half g_B[(size_t)N_DIM * D_DIM];   // unit-normalized labels
__device__ int    g_tile_ctr;                   // persistent-CTA work counter

// ---------------- PTX helpers (base PTX only) ----------------
__device__ __forceinline__ uint32_t smem_u32(const void* p) {
    uint32_t a;
    asm("{ .reg .u64 t; cvta.to.shared.u64 t, %1; cvt.u32.u64 %0, t; }"
        : "=r"(a) : "l"(p));
    return a;
}

#define CP_ASYNC16(s, g) \
    asm volatile("cp.async.cg.shared.global [%0], [%1], 16;" \
                 :: "r"(s), "l"(g) : "memory")
#define CP_COMMIT() asm volatile("cp.async.commit_group;" ::: "memory")
#define CP_WAIT(n)  asm volatile("cp.async.wait_group %0;" :: "n"(n) : "memory")

#define LDMATRIX_X4(r, addr) \
    asm volatile("ldmatrix.sync.aligned.m8n8.x4.shared.b16 {%0,%1,%2,%3}, [%4];" \
                 : "=r"((r)[0]), "=r"((r)[1]), "=r"((r)[2]), "=r"((r)[3]) \
                 : "r"(addr))

#define MMA16816(d, a, b0, b1) \
    asm volatile("mma.sync.aligned.m16n8k16.row.col.f32.f16.f16.f32 " \
                 "{%0,%1,%2,%3}, {%4,%5,%6,%7}, {%8,%9}, {%0,%1,%2,%3};" \
                 : "+f"((d)[0]), "+f"((d)[1]), "+f"((d)[2]), "+f"((d)[3]) \
                 : "r"((a)[0]), "r"((a)[1]), "r"((a)[2]), "r"((a)[3]), \
                   "r"(b0), "r"(b1))

// Sign-aware float atomic max (out initialized to -1.0; values in [-1, 1])
__device__ __forceinline__ void atomicMaxF(float* addr, float v) {
    if (v >= 0.0f) atomicMax((int*)addr, __float_as_int(v));
    else           atomicMin((unsigned int*)addr, __float_as_uint(v));
}

// Swizzled byte offset inside a tile: row r (128B rows), 16B chunk c in 0..7
__device__ __forceinline__ uint32_t swz(int r, int c) {
    return (uint32_t)(r * 128 + ((c ^ (r & 7)) << 4));
}

// ---------------- fused prep: ctr reset + out init + unit-norm fp16 ---------
// One warp per row; rows [0, M) -> embed->g_A, rows [M, M+N) -> label->g_B.
__global__ void prep_kernel(const float* __restrict__ embed,
                            const float* __restrict__ label,
                            float* __restrict__ out) {
    int gtid = blockIdx.x * blockDim.x + threadIdx.x;
    if (gtid == 0) g_tile_ctr = GRIDX;      // reset work counter every launch
    if (gtid < B_DIM * L_DIM) out[gtid] = -1.0f;
    int w = gtid >> 5;
    int lane = threadIdx.x & 31;
    const float* src;
    __half* dst;
    if (w < M_DIM)                 { src = embed + (size_t)w * D_DIM;
                                     dst = g_A + (size_t)w * D_DIM; }
    else if (w < M_DIM + N_DIM)    { src = label + (size_t)(w - M_DIM) * D_DIM;
                                     dst = g_B + (size_t)(w - M_DIM) * D_DIM; }
    else return;

    const float4* p = reinterpret_cast<const float4*>(src);
    float4 v[6];
    float s = 0.0f;
#pragma unroll
    for (int j = 0; j < 6; j++) {
        v[j] = p[lane + 32 * j];
        s += v[j].x * v[j].x + v[j].y * v[j].y + v[j].z * v[j].z + v[j].w * v[j].w;
    }
#pragma unroll
    for (int o = 16; o > 0; o >>= 1) s += __shfl_xor_sync(0xffffffffu, s, o);
    float inv = 1.0f / sqrtf(s);   // norms ~27.7, eps clamp never active
#pragma unroll
    for (int j = 0; j < 6; j++) {
        __half2 h0 = __floats2half2_rn(v[j].x * inv, v[j].y * inv);
        __half2 h1 = __floats2half2_rn(v[j].z * inv, v[j].w * inv);
        size_t base = (size_t)(lane + 32 * j) * 4;
        *reinterpret_cast<__half2*>(dst + base)     = h0;
        *reinterpret_cast<__half2*>(dst + base + 2) = h1;
    }
}

// ---------------- persistent HMMA GEMM + max epilogue ----------------
// R14 core (2-stage, one barrier per chunk), made persistent: 592 CTAs pull
// tiles from g_tile_ctr. 12 chunks/tile is even -> stage parity c&1 holds
// across tiles, so next tile's chunks 0,1 prefetch during chunks 10,11.
__global__ __launch_bounds__(NTHREADS)
void gemm_mma_kernel(const __half* __restrict__ A, const __half* __restrict__ Bm,
                     float* __restrict__ out) {
    extern __shared__ char smem[];
    __shared__ int sh_nt;
    const uint32_t sb = smem_u32(smem);
    const int tid = threadIdx.x;
    const int wid = tid >> 5;
    const int lane = tid & 31;
    const int wm = wid >> 1;            // 0..1  (m: 64-row slab)
    const int wn = wid & 1;             // 0..1  (n: 32-col slab)

    auto loadChunk = [&](int stage, int lm0, int ln0, int c) {
        const uint32_t base = sb + stage * BUF_BYTES;
#pragma unroll
        for (int j = 0; j < 8; j++) {                  // A: 128 rows x 128B
            int f = j * NTHREADS + tid;
            int r = f >> 3, cc = f & 7;
            const __half* g = A + (size_t)(lm0 + r) * D_DIM + c * KC + cc * 8;
            CP_ASYNC16(base + swz(r, cc), g);
        }
#pragma unroll
        for (int j = 0; j < 4; j++) {                  // B: 64 rows x 128B
            int f = j * NTHREADS + tid;
            int r = f >> 3, cc = f & 7;
            const __half* g = Bm + (size_t)(ln0 + r) * D_DIM + c * KC + cc * 8;
            CP_ASYNC16(base + A_BYTES + swz(r, cc), g);
        }
    };

    int cur = blockIdx.x;               // first tile = own bid (ctr starts at GRIDX)
    if (cur >= NTILE) return;
    int bx = cur % NTILE_X, by = cur / NTILE_X;
    int m0 = by * BM, n0 = bx * BN;

    loadChunk(0, m0, n0, 0); CP_COMMIT();
    loadChunk(1, m0, n0, 1); CP_COMMIT();
    CP_WAIT(1);            // chunk 0 complete (chunk 1 still in flight)
    __syncthreads();       // chunk 0 visible to all warps

    float acc[4][4][4];
#pragma unroll
    for (int mi = 0; mi < 4; mi++)
#pragma unroll
        for (int ni = 0; ni < 4; ni++)
#pragma unroll
            for (int e = 0; e < 4; e++) acc[mi][ni][e] = 0.0f;

    const int t = lane >> 3;            // ldmatrix tile index 0..3
    const int lr = lane & 7;            // row within 8-row tile

    while (true) {
        const int l0 = bx * (BN / V_DIM);
        int nt = NTILE;                 // next tile (fetched at c==8)

#pragma unroll 1
        for (int c = 0; c < NCHUNK; c++) {
            const uint32_t ab = sb + (c & 1) * BUF_BYTES;
            const uint32_t bb = ab + A_BYTES;
#pragma unroll
            for (int ks = 0; ks < 4; ks++) {      // four k16 steps per chunk
                uint32_t afr[4][4], bfr[2][4];
#pragma unroll
                for (int mi = 0; mi < 4; mi++) {
                    int r = wm * 64 + mi * 16 + lr + ((t & 1) << 3);
                    int cc = ks * 2 + (t >> 1);
                    LDMATRIX_X4(afr[mi], ab + swz(r, cc));
                }
#pragma unroll
                for (int p = 0; p < 2; p++) {
                    int r = wn * 32 + p * 16 + lr + ((t >> 1) << 3);
                    int cc = ks * 2 + (t & 1);
                    LDMATRIX_X4(bfr[p], bb + swz(r, cc));
                }
#pragma unroll
                for (int mi = 0; mi < 4; mi++)
#pragma unroll
                    for (int ni = 0; ni < 4; ni++)
                        MMA16816(acc[mi][ni], afr[mi],
                                 bfr[ni >> 1][(ni & 1) * 2],
                                 bfr[ni >> 1][(ni & 1) * 2 + 1]);
            }

            if (c == 8 && tid == 0) sh_nt = atomicAdd(&g_tile_ctr, 1);

            CP_WAIT(0);        // chunk c+1 (or next tile's) complete
            __syncthreads();   // visible to all warps; stage c&1 reusable;
                               // also publishes sh_nt written at c==8
            if (c <= 9) {
                loadChunk(c & 1, m0, n0, c + 2); CP_COMMIT();
            } else {
                if (c == 10) nt = sh_nt;
                if (nt < NTILE) {   // prefetch next tile's chunk 0 / 1
                    int nbx = nt % NTILE_X, nby = nt / NTILE_X;
                    loadChunk(c & 1, nby * BM, nbx * BN, c - 10); CP_COMMIT();
                }
            }
        }

        // ---- epilogue: each n8 fragment == one label; reduce v via shfl ----
        const int g  = lane >> 2;       // fragment row group 0..7
        const int tq = lane & 3;        // v-pair owner 0..3
#pragma unroll
        for (int mi = 0; mi < 4; mi++) {
            const int b0 = wm * 64 + mi * 16 + g;  // local row == batch b
#pragma unroll
            for (int ni = 0; ni < 4; ni++) {
                float mx0 = fmaxf(acc[mi][ni][0], acc[mi][ni][1]);   // row b0
                float mx1 = fmaxf(acc[mi][ni][2], acc[mi][ni][3]);   // row b0+8
#pragma unroll
                for (int o = 1; o < 4; o <<= 1) {  // all 8 v of this label
                    mx0 = fmaxf(mx0, __shfl_xor_sync(0xffffffffu, mx0, o));
                    mx1 = fmaxf(mx1, __shfl_xor_sync(0xffffffffu, mx1, o));
                }
                if (tq == 0) {
                    int l = l0 + wn * 4 + ni;
                    atomicMaxF(out + b0 * L_DIM + l, mx0);
                    atomicMaxF(out + (b0 + 8) * L_DIM + l, mx1);
                }
                acc[mi][ni][0] = 0.0f; acc[mi][ni][1] = 0.0f;
                acc[mi][ni][2] = 0.0f; acc[mi][ni][3] = 0.0f;
            }
        }

        cur = nt;
        if (cur >= NTILE) break;
        bx = cur % NTILE_X; by = cur / NTILE_X;
        m0 = by * BM; n0 = bx * BN;
        // chunks 0,1 of this tile are already loaded/in flight; the loop's
        // c==0 iteration computes from stage 0, whose data arrived and was
        // synced by the previous tile's c==10 wait/sync and c==11 barrier.
    }
}

extern "C" void kernel_launch(void* const* d_in, const int* in_sizes, int n_in,
                              void* d_out, int out_size) {
    const float* embed = (const float*)d_in[0];   // [256,128,768]
    const float* label = (const float*)d_in[1];   // [200,8,768]
    float* out = (float*)d_out;                   // [128,200]

    __half *d_A, *d_B;
    cudaGetSymbolAddress((void**)&d_A, g_A);
    cudaGetSymbolAddress((void**)&d_B, g_B);

    (void)cudaFuncSetAttribute(gemm_mma_kernel,
                               cudaFuncAttributeMaxDynamicSharedMemorySize,
                               SMEM_TOTAL);

    // one prep launch: ctr reset + out init + A/B normalize (8 warps/block)
    prep_kernel<<<(M_DIM + N_DIM) / 8, 256>>>(embed, label, out);

    gemm_mma_kernel<<<GRIDX, NTHREADS, SMEM_TOTAL>>>(d_A, d_B, out);
}